// round 1
// baseline (speedup 1.0000x reference)
#include <cuda_runtime.h>
#include <math.h>

#define LSEQ 200
#define B_MAX 4096

// scratch for x = concat(u_emb, i_emb, c_emb, d_emb, user_dense, item_dense, pooled) : 244 per sample
__device__ float g_xbuf[B_MAX * 244];

struct SmemA {
    float t[64];
    float c[64];
    float M[64 * 64];        // M[k*64 + j]
    float aW1s[64 * 32];     // [k*32 + j]
    float aW2s[32];
    float ab1s[32];
    float scores[208];
    float red[32];
    float pool4[256];
    float spart[16 * 64];    // per-jg partial scores for deterministic reduction
    float histT[64 * 204];   // histT[k*204 + l], cols 200..203 zero
    float h0T[64 * 64];      // swizzled: h0T[k*64 + ((l>>2)^(k&15))*4 + (l&3)]
};

__global__ __launch_bounds__(256, 2) void attn_kernel(
    const int* __restrict__ user_id, const int* __restrict__ item_id,
    const int* __restrict__ item_category, const int* __restrict__ item_dur_bkt,
    const float* __restrict__ user_dense, const float* __restrict__ item_dense,
    const int* __restrict__ history_seq,
    const float* __restrict__ user_W, const float* __restrict__ item_W,
    const float* __restrict__ cat_W, const float* __restrict__ dur_W,
    const float* __restrict__ hist_W,
    const float* __restrict__ aW0, const float* __restrict__ ab0,
    const float* __restrict__ aW1, const float* __restrict__ ab1,
    const float* __restrict__ aW2, const float* __restrict__ ab2)
{
    extern __shared__ char smem_raw[];
    SmemA& S = *reinterpret_cast<SmemA*>(smem_raw);
    const int b = blockIdx.x;
    const int tid = threadIdx.x;

    // ---- load item embedding t, attention weights, init scores with ab2 ----
    if (tid < 64) S.t[tid] = item_W[item_id[b] * 64 + tid];
    for (int p = tid; p < 2048; p += 256) S.aW1s[p] = aW1[p];
    if (tid < 32) { S.aW2s[tid] = aW2[tid]; S.ab1s[tid] = ab1[tid]; }
    {
        float ab2v = ab2[0];
        for (int p = tid; p < 208; p += 256) S.scores[p] = ab2v;
    }
    __syncthreads();

    // ---- build M_b[k][j] = aW0[k][j] + aW0[192+k][j] + t[k]*aW0[128+k][j] ----
    for (int idx = tid; idx < 4096; idx += 256) {
        int k = idx >> 6, j = idx & 63;
        S.M[idx] = aW0[idx] + aW0[(192 + k) * 64 + j] + S.t[k] * aW0[(128 + k) * 64 + j];
    }
    // ---- c_b[j] = ab0[j] + sum_k t[k]*(aW0[64+k][j] - aW0[192+k][j]) ----
    if (tid < 64) {
        float s = ab0[tid];
        #pragma unroll 8
        for (int k = 0; k < 64; k++)
            s += S.t[k] * (aW0[(64 + k) * 64 + tid] - aW0[(192 + k) * 64 + tid]);
        S.c[tid] = s;
    }
    // ---- gather history rows (transposed into histT) ----
    {
        int wid = tid >> 5, lane = tid & 31;
        for (int l = wid; l < LSEQ; l += 8) {
            int row = history_seq[b * LSEQ + l];
            float2 v = *(const float2*)&hist_W[row * 64 + lane * 2];
            S.histT[(lane * 2) * 204 + l]     = v.x;
            S.histT[(lane * 2 + 1) * 204 + l] = v.y;
        }
    }
    for (int p = tid; p < 64 * 4; p += 256)
        S.histT[(p >> 2) * 204 + 200 + (p & 3)] = 0.f;
    __syncthreads();

    // ---- attention GEMMs in chunks of 64 l ----
    const int lg = tid >> 4;          // 0..15
    const int jg = tid & 15;          // 0..15
    const int j0 = jg << 2;

    for (int l0c = 0; l0c < LSEQ; l0c += 64) {
        int l0 = l0c + (lg << 2);
        // GEMM1: h0[l][j] = relu( sum_k histT[k][l] * M[k][j] + c[j] )
        if (l0 < 204) {
            float acc[4][4];
            #pragma unroll
            for (int jj = 0; jj < 4; jj++) {
                float cv = S.c[j0 + jj];
                acc[0][jj] = cv; acc[1][jj] = cv; acc[2][jj] = cv; acc[3][jj] = cv;
            }
            const float* hptr = &S.histT[l0];
            const float* mptr = &S.M[j0];
            #pragma unroll 8
            for (int k = 0; k < 64; k++) {
                float4 av = *(const float4*)(hptr + k * 204);
                float4 bv = *(const float4*)(mptr + (k << 6));
                acc[0][0] += av.x * bv.x; acc[0][1] += av.x * bv.y; acc[0][2] += av.x * bv.z; acc[0][3] += av.x * bv.w;
                acc[1][0] += av.y * bv.x; acc[1][1] += av.y * bv.y; acc[1][2] += av.y * bv.z; acc[1][3] += av.y * bv.w;
                acc[2][0] += av.z * bv.x; acc[2][1] += av.z * bv.y; acc[2][2] += av.z * bv.z; acc[2][3] += av.z * bv.w;
                acc[3][0] += av.w * bv.x; acc[3][1] += av.w * bv.y; acc[3][2] += av.w * bv.z; acc[3][3] += av.w * bv.w;
            }
            #pragma unroll
            for (int jj = 0; jj < 4; jj++) {
                int j = j0 + jj;
                int cg = lg ^ (j & 15);
                float4 v = make_float4(fmaxf(acc[0][jj], 0.f), fmaxf(acc[1][jj], 0.f),
                                       fmaxf(acc[2][jj], 0.f), fmaxf(acc[3][jj], 0.f));
                *(float4*)&S.h0T[(j << 6) + (cg << 2)] = v;
            }
        }
        __syncthreads();

        // GEMM2: h1[l][j2] = relu( sum_k h0[l][k]*aW1[k][j2] + ab1[j2] ); partial score into spart
        {
            int l0b = l0c + (lg << 2);
            int j0b = jg << 1;
            if (l0b < 204) {
                float a2[4][2];
                float b0v = S.ab1s[j0b], b1v = S.ab1s[j0b + 1];
                #pragma unroll
                for (int li = 0; li < 4; li++) { a2[li][0] = b0v; a2[li][1] = b1v; }
                #pragma unroll 8
                for (int k = 0; k < 64; k++) {
                    int cg = lg ^ (k & 15);
                    float4 av = *(const float4*)&S.h0T[(k << 6) + (cg << 2)];
                    float2 wv = *(const float2*)&S.aW1s[(k << 5) + j0b];
                    a2[0][0] += av.x * wv.x; a2[0][1] += av.x * wv.y;
                    a2[1][0] += av.y * wv.x; a2[1][1] += av.y * wv.y;
                    a2[2][0] += av.z * wv.x; a2[2][1] += av.z * wv.y;
                    a2[3][0] += av.w * wv.x; a2[3][1] += av.w * wv.y;
                }
                float w0 = S.aW2s[j0b], w1 = S.aW2s[j0b + 1];
                #pragma unroll
                for (int li = 0; li < 4; li++) {
                    float p = fmaxf(a2[li][0], 0.f) * w0 + fmaxf(a2[li][1], 0.f) * w1;
                    S.spart[jg * 64 + (lg << 2) + li] = p;
                }
            }
        }
        __syncthreads();
        // deterministic reduction of 16 jg-partials into scores
        if (tid < 64) {
            int l = l0c + tid;
            if (l < LSEQ) {
                float ssum = 0.f;
                #pragma unroll
                for (int q = 0; q < 16; q++) ssum += S.spart[q * 64 + tid];
                S.scores[l] += ssum;
            }
        }
        __syncthreads();
    }

    // ---- mask + softmax over L ----
    float e;
    {
        float s = -3.402823466e38f;
        if (tid < LSEQ) {
            s = S.scores[tid];
            if (history_seq[b * LSEQ + tid] == 0) s = -1.0e9f;
        }
        float v = s;
        #pragma unroll
        for (int o = 16; o; o >>= 1) v = fmaxf(v, __shfl_xor_sync(0xffffffffu, v, o));
        if ((tid & 31) == 0) S.red[tid >> 5] = v;
        __syncthreads();
        if (tid < 32) {
            float r = (tid < 8) ? S.red[tid] : -3.402823466e38f;
            #pragma unroll
            for (int o = 4; o; o >>= 1) r = fmaxf(r, __shfl_xor_sync(0xffffffffu, r, o));
            if (tid == 0) S.red[8] = r;
        }
        __syncthreads();
        float mx = S.red[8];
        e = (tid < LSEQ) ? expf(s - mx) : 0.f;
        float v2 = e;
        #pragma unroll
        for (int o = 16; o; o >>= 1) v2 += __shfl_xor_sync(0xffffffffu, v2, o);
        if ((tid & 31) == 0) S.red[tid >> 5] = v2;
        __syncthreads();
        if (tid < 32) {
            float r = (tid < 8) ? S.red[tid] : 0.f;
            #pragma unroll
            for (int o = 4; o; o >>= 1) r += __shfl_xor_sync(0xffffffffu, r, o);
            if (tid == 0) S.red[8] = r;
        }
        __syncthreads();
        float inv = 1.f / S.red[8];
        if (tid < LSEQ) S.scores[tid] = e * inv;
    }
    __syncthreads();

    // ---- pooled[k] = sum_l w[l] * histT[k][l] ----
    {
        int k = tid & 63, g = tid >> 6;
        float p = 0.f;
        for (int l = g; l < LSEQ; l += 4) p += S.histT[k * 204 + l] * S.scores[l];
        S.pool4[(g << 6) + k] = p;
    }
    __syncthreads();
    if (tid < 64) {
        float pooled = S.pool4[tid] + S.pool4[64 + tid] + S.pool4[128 + tid] + S.pool4[192 + tid];
        g_xbuf[b * 244 + 180 + tid] = pooled;
    }
    // ---- assemble remaining features of x ----
    if (tid < 64) {
        g_xbuf[b * 244 + tid] = user_W[user_id[b] * 64 + tid];
    } else if (tid < 128) {
        g_xbuf[b * 244 + tid] = S.t[tid - 64];                      // offset 64
    } else if (tid < 144) {
        g_xbuf[b * 244 + tid] = cat_W[item_category[b] * 16 + (tid - 128)];   // offset 128
    } else if (tid < 152) {
        g_xbuf[b * 244 + tid] = dur_W[item_dur_bkt[b] * 8 + (tid - 144)];     // offset 144
    } else if (tid < 177) {
        g_xbuf[b * 244 + tid] = user_dense[b * 25 + (tid - 152)];   // offset 152
    } else if (tid < 180) {
        g_xbuf[b * 244 + tid] = item_dense[b * 3 + (tid - 177)];    // offset 177
    }
}

__global__ __launch_bounds__(256) void mlp_kernel(
    const float* __restrict__ mW0, const float* __restrict__ mb0,
    const float* __restrict__ mW1, const float* __restrict__ mb1,
    const float* __restrict__ mW2, const float* __restrict__ mb2,
    float* __restrict__ out, int B)
{
    __shared__ float xs[16 * 244];
    __shared__ float h0s[16 * 256];
    __shared__ float h1s[16 * 128];
    const int b0 = blockIdx.x * 16;
    const int tid = threadIdx.x;
    const int nb = (B - b0 < 16) ? (B - b0) : 16;

    for (int p = tid; p < nb * 244; p += 256) xs[p] = g_xbuf[b0 * 244 + p];
    __syncthreads();

    // layer 0: 244 -> 256
    {
        float acc[16];
        float bias = mb0[tid];
        #pragma unroll
        for (int q = 0; q < 16; q++) acc[q] = bias;
        for (int i = 0; i < 244; i++) {
            float w = mW0[i * 256 + tid];
            #pragma unroll
            for (int q = 0; q < 16; q++) acc[q] += xs[q * 244 + i] * w;
        }
        #pragma unroll
        for (int q = 0; q < 16; q++) h0s[q * 256 + tid] = fmaxf(acc[q], 0.f);
    }
    __syncthreads();

    // layer 1: 256 -> 128 (two thread-halves handle 8 samples each)
    {
        int j = tid & 127, h = tid >> 7;
        float acc[8];
        float bias = mb1[j];
        #pragma unroll
        for (int q = 0; q < 8; q++) acc[q] = bias;
        const float* h0p = &h0s[(h * 8) * 256];
        for (int i = 0; i < 256; i++) {
            float w = mW1[i * 128 + j];
            #pragma unroll
            for (int q = 0; q < 8; q++) acc[q] += h0p[q * 256 + i] * w;
        }
        #pragma unroll
        for (int q = 0; q < 8; q++) h1s[(h * 8 + q) * 128 + j] = fmaxf(acc[q], 0.f);
    }
    __syncthreads();

    // layer 2: 128 -> 1, sigmoid
    {
        int w = tid >> 5, lane = tid & 31;
        float m0 = mW2[lane], m1 = mW2[lane + 32], m2 = mW2[lane + 64], m3 = mW2[lane + 96];
        for (int bb = w; bb < 16; bb += 8) {
            const float* hp = &h1s[bb * 128];
            float v = hp[lane] * m0 + hp[lane + 32] * m1 + hp[lane + 64] * m2 + hp[lane + 96] * m3;
            #pragma unroll
            for (int o = 16; o; o >>= 1) v += __shfl_xor_sync(0xffffffffu, v, o);
            if (lane == 0 && (b0 + bb) < B) {
                float logit = v + mb2[0];
                out[b0 + bb] = 1.f / (1.f + expf(-logit));
            }
        }
    }
}

extern "C" void kernel_launch(void* const* d_in, const int* in_sizes, int n_in,
                              void* d_out, int out_size)
{
    const int*   user_id       = (const int*)d_in[0];
    const int*   item_id       = (const int*)d_in[1];
    const int*   item_category = (const int*)d_in[2];
    const int*   item_dur_bkt  = (const int*)d_in[3];
    const float* user_dense    = (const float*)d_in[4];
    const float* item_dense    = (const float*)d_in[5];
    const int*   history_seq   = (const int*)d_in[6];
    const float* user_W        = (const float*)d_in[7];
    const float* item_W        = (const float*)d_in[8];
    const float* cat_W         = (const float*)d_in[9];
    const float* dur_W         = (const float*)d_in[10];
    const float* hist_W        = (const float*)d_in[11];
    const float* aW0 = (const float*)d_in[12];
    const float* ab0 = (const float*)d_in[13];
    const float* aW1 = (const float*)d_in[14];
    const float* ab1 = (const float*)d_in[15];
    const float* aW2 = (const float*)d_in[16];
    const float* ab2 = (const float*)d_in[17];
    const float* mW0 = (const float*)d_in[18];
    const float* mb0 = (const float*)d_in[19];
    const float* mW1 = (const float*)d_in[20];
    const float* mb1 = (const float*)d_in[21];
    const float* mW2 = (const float*)d_in[22];
    const float* mb2 = (const float*)d_in[23];

    const int B = in_sizes[0];
    float* out = (float*)d_out;

    cudaFuncSetAttribute(attn_kernel, cudaFuncAttributeMaxDynamicSharedMemorySize,
                         (int)sizeof(SmemA));

    attn_kernel<<<B, 256, sizeof(SmemA)>>>(
        user_id, item_id, item_category, item_dur_bkt,
        user_dense, item_dense, history_seq,
        user_W, item_W, cat_W, dur_W, hist_W,
        aW0, ab0, aW1, ab1, aW2, ab2);

    mlp_kernel<<<(B + 15) / 16, 256>>>(mW0, mb0, mW1, mb1, mW2, mb2, out, B);
}

// round 2
// speedup vs baseline: 1.1079x; 1.1079x over previous
#include <cuda_runtime.h>
#include <math.h>

#define LSEQ 200
#define B_MAX 4096

// scratch for x = concat(...) : 244 per sample
__device__ float g_xbuf[B_MAX * 244];

typedef unsigned long long u64t;

__device__ __forceinline__ u64t dup2(float x) {
    u64t r; asm("mov.b64 %0, {%1, %1};" : "=l"(r) : "f"(x)); return r;
}
__device__ __forceinline__ void fma2(u64t& d, u64t a, u64t b) {
    asm("fma.rn.f32x2 %0, %1, %2, %0;" : "+l"(d) : "l"(a), "l"(b));
}
__device__ __forceinline__ void unpack2(u64t v, float& a, float& b) {
    asm("mov.b64 {%0, %1}, %2;" : "=f"(a), "=f"(b) : "l"(v));
}

struct __align__(16) SmemA {
    float histT[64 * 204];   // histT[k*204 + l], cols 200..203 zero
    float h0T[64 * 64];      // swizzled: h0T[j*64 + ((lg^(j&15))*4 + (l&3))]
    float M[64 * 64];        // M[k*64 + j]
    float aW1s[64 * 32];     // [k*32 + j2]
    float t[64];
    float c[64];
    float aW2s[32];
    float ab1s[32];
    float scores[208];
    float red[32];
    float pool4[256];
    float spart[16 * 64];    // per-jg partial scores
};

__global__ __launch_bounds__(256, 2) void attn_kernel(
    const int* __restrict__ user_id, const int* __restrict__ item_id,
    const int* __restrict__ item_category, const int* __restrict__ item_dur_bkt,
    const float* __restrict__ user_dense, const float* __restrict__ item_dense,
    const int* __restrict__ history_seq,
    const float* __restrict__ user_W, const float* __restrict__ item_W,
    const float* __restrict__ cat_W, const float* __restrict__ dur_W,
    const float* __restrict__ hist_W,
    const float* __restrict__ aW0, const float* __restrict__ ab0,
    const float* __restrict__ aW1, const float* __restrict__ ab1,
    const float* __restrict__ aW2, const float* __restrict__ ab2)
{
    extern __shared__ char smem_raw[];
    SmemA& S = *reinterpret_cast<SmemA*>(smem_raw);
    const int b = blockIdx.x;
    const int tid = threadIdx.x;

    // ---- load item embedding t, attention weights, init scores with ab2 ----
    if (tid < 64) S.t[tid] = item_W[item_id[b] * 64 + tid];
    for (int p = tid; p < 2048; p += 256) S.aW1s[p] = aW1[p];
    if (tid < 32) { S.aW2s[tid] = aW2[tid]; S.ab1s[tid] = ab1[tid]; }
    {
        float ab2v = ab2[0];
        for (int p = tid; p < 208; p += 256) S.scores[p] = ab2v;
    }
    __syncthreads();

    // ---- build M_b[k][j] = aW0[k][j] + aW0[192+k][j] + t[k]*aW0[128+k][j] ----
    for (int idx = tid; idx < 4096; idx += 256) {
        int k = idx >> 6, j = idx & 63;
        S.M[idx] = aW0[idx] + aW0[(192 + k) * 64 + j] + S.t[k] * aW0[(128 + k) * 64 + j];
    }
    // ---- c_b[j] = ab0[j] + sum_k t[k]*(aW0[64+k][j] - aW0[192+k][j]) ----
    if (tid < 64) {
        float s = ab0[tid];
        #pragma unroll 8
        for (int k = 0; k < 64; k++)
            s += S.t[k] * (aW0[(64 + k) * 64 + tid] - aW0[(192 + k) * 64 + tid]);
        S.c[tid] = s;
    }
    // ---- gather history rows (transposed into histT) ----
    {
        int wid = tid >> 5, lane = tid & 31;
        for (int l = wid; l < LSEQ; l += 8) {
            int row = history_seq[b * LSEQ + l];
            float2 v = *(const float2*)&hist_W[row * 64 + lane * 2];
            S.histT[(lane * 2) * 204 + l]     = v.x;
            S.histT[(lane * 2 + 1) * 204 + l] = v.y;
        }
    }
    for (int p = tid; p < 64 * 4; p += 256)
        S.histT[(p >> 2) * 204 + 200 + (p & 3)] = 0.f;
    __syncthreads();

    // ---- attention GEMMs in chunks of 64 l, packed f32x2 along l ----
    const int lg = tid >> 4;          // 0..15
    const int jg = tid & 15;          // 0..15
    const int j0 = jg << 2;
    const int j0b = jg << 1;

    for (int l0c = 0; l0c < LSEQ; l0c += 64) {
        int l0 = l0c + (lg << 2);
        // GEMM1: h0[l][j] = relu( sum_k histT[k][l] * M[k][j] + c[j] )
        if (l0 < 204) {
            u64t acc[2][4];
            #pragma unroll
            for (int jj = 0; jj < 4; jj++) {
                u64t cv = dup2(S.c[j0 + jj]);
                acc[0][jj] = cv; acc[1][jj] = cv;
            }
            const float* hptr = &S.histT[l0];
            const float* mptr = &S.M[j0];
            #pragma unroll 8
            for (int k = 0; k < 64; k++) {
                ulonglong2 av = *(const ulonglong2*)(hptr + k * 204);
                float4 bv = *(const float4*)(mptr + (k << 6));
                u64t b0d = dup2(bv.x), b1d = dup2(bv.y), b2d = dup2(bv.z), b3d = dup2(bv.w);
                fma2(acc[0][0], av.x, b0d); fma2(acc[1][0], av.y, b0d);
                fma2(acc[0][1], av.x, b1d); fma2(acc[1][1], av.y, b1d);
                fma2(acc[0][2], av.x, b2d); fma2(acc[1][2], av.y, b2d);
                fma2(acc[0][3], av.x, b3d); fma2(acc[1][3], av.y, b3d);
            }
            #pragma unroll
            for (int jj = 0; jj < 4; jj++) {
                int j = j0 + jj;
                int cg = lg ^ (j & 15);
                float v0, v1, v2, v3;
                unpack2(acc[0][jj], v0, v1);
                unpack2(acc[1][jj], v2, v3);
                float4 v = make_float4(fmaxf(v0, 0.f), fmaxf(v1, 0.f),
                                       fmaxf(v2, 0.f), fmaxf(v3, 0.f));
                *(float4*)&S.h0T[(j << 6) + (cg << 2)] = v;
            }
        }
        __syncthreads();

        // GEMM2: h1[l][j2] = relu( sum_k h0[l][k]*aW1[k][j2] + ab1[j2] ); partial score
        if (l0 < 204) {
            u64t bi0 = dup2(S.ab1s[j0b]), bi1 = dup2(S.ab1s[j0b + 1]);
            u64t acc[2][2] = {{bi0, bi1}, {bi0, bi1}};
            #pragma unroll 8
            for (int k = 0; k < 64; k++) {
                int cg = lg ^ (k & 15);
                ulonglong2 av = *(const ulonglong2*)&S.h0T[(k << 6) + (cg << 2)];
                float2 wv = *(const float2*)&S.aW1s[(k << 5) + j0b];
                u64t w0d = dup2(wv.x), w1d = dup2(wv.y);
                fma2(acc[0][0], av.x, w0d); fma2(acc[1][0], av.y, w0d);
                fma2(acc[0][1], av.x, w1d); fma2(acc[1][1], av.y, w1d);
            }
            float w20 = S.aW2s[j0b], w21 = S.aW2s[j0b + 1];
            #pragma unroll
            for (int p = 0; p < 2; p++) {
                float h00, h01, h10, h11;
                unpack2(acc[p][0], h00, h01);
                unpack2(acc[p][1], h10, h11);
                float p0 = fmaxf(h00, 0.f) * w20 + fmaxf(h10, 0.f) * w21;
                float p1 = fmaxf(h01, 0.f) * w20 + fmaxf(h11, 0.f) * w21;
                S.spart[jg * 64 + (lg << 2) + 2 * p]     = p0;
                S.spart[jg * 64 + (lg << 2) + 2 * p + 1] = p1;
            }
        }
        __syncthreads();
        // deterministic reduction of 16 jg-partials into scores
        if (tid < 64) {
            int l = l0c + tid;
            if (l < LSEQ) {
                float ssum = 0.f;
                #pragma unroll
                for (int q = 0; q < 16; q++) ssum += S.spart[q * 64 + tid];
                S.scores[l] += ssum;
            }
        }
        __syncthreads();
    }

    // ---- mask + softmax over L ----
    {
        float s = -3.402823466e38f;
        if (tid < LSEQ) {
            s = S.scores[tid];
            if (history_seq[b * LSEQ + tid] == 0) s = -1.0e9f;
        }
        float v = s;
        #pragma unroll
        for (int o = 16; o; o >>= 1) v = fmaxf(v, __shfl_xor_sync(0xffffffffu, v, o));
        if ((tid & 31) == 0) S.red[tid >> 5] = v;
        __syncthreads();
        if (tid < 32) {
            float r = (tid < 8) ? S.red[tid] : -3.402823466e38f;
            #pragma unroll
            for (int o = 4; o; o >>= 1) r = fmaxf(r, __shfl_xor_sync(0xffffffffu, r, o));
            if (tid == 0) S.red[8] = r;
        }
        __syncthreads();
        float mx = S.red[8];
        float e = (tid < LSEQ) ? expf(s - mx) : 0.f;
        float v2 = e;
        #pragma unroll
        for (int o = 16; o; o >>= 1) v2 += __shfl_xor_sync(0xffffffffu, v2, o);
        if ((tid & 31) == 0) S.red[tid >> 5] = v2;
        __syncthreads();
        if (tid < 32) {
            float r = (tid < 8) ? S.red[tid] : 0.f;
            #pragma unroll
            for (int o = 4; o; o >>= 1) r += __shfl_xor_sync(0xffffffffu, r, o);
            if (tid == 0) S.red[8] = r;
        }
        __syncthreads();
        float inv = 1.f / S.red[8];
        if (tid < LSEQ) S.scores[tid] = e * inv;
    }
    __syncthreads();

    // ---- pooled[k] = sum_l w[l] * histT[k][l] ----
    {
        int k = tid & 63, g = tid >> 6;
        float p = 0.f;
        for (int l = g; l < LSEQ; l += 4) p += S.histT[k * 204 + l] * S.scores[l];
        S.pool4[(g << 6) + k] = p;
    }
    __syncthreads();
    if (tid < 64) {
        float pooled = S.pool4[tid] + S.pool4[64 + tid] + S.pool4[128 + tid] + S.pool4[192 + tid];
        g_xbuf[b * 244 + 180 + tid] = pooled;
    }
    // ---- assemble remaining features of x ----
    if (tid < 64) {
        g_xbuf[b * 244 + tid] = user_W[user_id[b] * 64 + tid];
    } else if (tid < 128) {
        g_xbuf[b * 244 + tid] = S.t[tid - 64];
    } else if (tid < 144) {
        g_xbuf[b * 244 + tid] = cat_W[item_category[b] * 16 + (tid - 128)];
    } else if (tid < 152) {
        g_xbuf[b * 244 + tid] = dur_W[item_dur_bkt[b] * 8 + (tid - 144)];
    } else if (tid < 177) {
        g_xbuf[b * 244 + tid] = user_dense[b * 25 + (tid - 152)];
    } else if (tid < 180) {
        g_xbuf[b * 244 + tid] = item_dense[b * 3 + (tid - 177)];
    }
}

// ---- MLP: 8 samples per block, samples packed along f32x2 ----
__global__ __launch_bounds__(256) void mlp_kernel(
    const float* __restrict__ mW0, const float* __restrict__ mb0,
    const float* __restrict__ mW1, const float* __restrict__ mb1,
    const float* __restrict__ mW2, const float* __restrict__ mb2,
    float* __restrict__ out, int B)
{
    __shared__ __align__(16) float xsT[244 * 8];   // [i][q]
    __shared__ __align__(16) float h0T[256 * 8];   // [i2][q]
    __shared__ __align__(16) float h1s[8 * 128];   // [q][j]
    const int b0 = blockIdx.x * 8;
    const int tid = threadIdx.x;

    // load + transpose x
    #pragma unroll
    for (int q = 0; q < 8; q++) {
        if (tid < 244 && (b0 + q) < B)
            xsT[tid * 8 + q] = g_xbuf[(b0 + q) * 244 + tid];
    }
    __syncthreads();

    // layer 0: 244 -> 256, thread = output col, 8 samples as 4 f32x2 pairs
    {
        u64t acc[4];
        u64t bias = dup2(mb0[tid]);
        #pragma unroll
        for (int p = 0; p < 4; p++) acc[p] = bias;
        #pragma unroll 4
        for (int i = 0; i < 244; i++) {
            u64t wd = dup2(mW0[i * 256 + tid]);
            ulonglong2 x01 = *(const ulonglong2*)&xsT[i * 8];
            ulonglong2 x23 = *(const ulonglong2*)&xsT[i * 8 + 4];
            fma2(acc[0], x01.x, wd); fma2(acc[1], x01.y, wd);
            fma2(acc[2], x23.x, wd); fma2(acc[3], x23.y, wd);
        }
        #pragma unroll
        for (int p = 0; p < 4; p++) {
            float a, c;
            unpack2(acc[p], a, c);
            h0T[tid * 8 + 2 * p]     = fmaxf(a, 0.f);
            h0T[tid * 8 + 2 * p + 1] = fmaxf(c, 0.f);
        }
    }
    __syncthreads();

    // layer 1: 256 -> 128; j = tid&127, half h = tid>>7 handles 4 samples (2 pairs)
    {
        int j = tid & 127, h = tid >> 7;
        u64t bias = dup2(mb1[j]);
        u64t acc[2] = {bias, bias};
        #pragma unroll 4
        for (int i = 0; i < 256; i++) {
            u64t wd = dup2(mW1[i * 128 + j]);
            ulonglong2 a = *(const ulonglong2*)&h0T[i * 8 + h * 4];
            fma2(acc[0], a.x, wd); fma2(acc[1], a.y, wd);
        }
        #pragma unroll
        for (int p = 0; p < 2; p++) {
            float a, c;
            unpack2(acc[p], a, c);
            h1s[(h * 4 + 2 * p) * 128 + j]     = fmaxf(a, 0.f);
            h1s[(h * 4 + 2 * p + 1) * 128 + j] = fmaxf(c, 0.f);
        }
    }
    __syncthreads();

    // layer 2: 128 -> 1, sigmoid; one warp per sample
    {
        int w = tid >> 5, lane = tid & 31;
        float m0 = mW2[lane], m1 = mW2[lane + 32], m2 = mW2[lane + 64], m3 = mW2[lane + 96];
        const float* hp = &h1s[w * 128];
        float v = hp[lane] * m0 + hp[lane + 32] * m1 + hp[lane + 64] * m2 + hp[lane + 96] * m3;
        #pragma unroll
        for (int o = 16; o; o >>= 1) v += __shfl_xor_sync(0xffffffffu, v, o);
        if (lane == 0 && (b0 + w) < B) {
            float logit = v + mb2[0];
            out[b0 + w] = 1.f / (1.f + expf(-logit));
        }
    }
}

extern "C" void kernel_launch(void* const* d_in, const int* in_sizes, int n_in,
                              void* d_out, int out_size)
{
    const int*   user_id       = (const int*)d_in[0];
    const int*   item_id       = (const int*)d_in[1];
    const int*   item_category = (const int*)d_in[2];
    const int*   item_dur_bkt  = (const int*)d_in[3];
    const float* user_dense    = (const float*)d_in[4];
    const float* item_dense    = (const float*)d_in[5];
    const int*   history_seq   = (const int*)d_in[6];
    const float* user_W        = (const float*)d_in[7];
    const float* item_W        = (const float*)d_in[8];
    const float* cat_W         = (const float*)d_in[9];
    const float* dur_W         = (const float*)d_in[10];
    const float* hist_W        = (const float*)d_in[11];
    const float* aW0 = (const float*)d_in[12];
    const float* ab0 = (const float*)d_in[13];
    const float* aW1 = (const float*)d_in[14];
    const float* ab1 = (const float*)d_in[15];
    const float* aW2 = (const float*)d_in[16];
    const float* ab2 = (const float*)d_in[17];
    const float* mW0 = (const float*)d_in[18];
    const float* mb0 = (const float*)d_in[19];
    const float* mW1 = (const float*)d_in[20];
    const float* mb1 = (const float*)d_in[21];
    const float* mW2 = (const float*)d_in[22];
    const float* mb2 = (const float*)d_in[23];

    const int B = in_sizes[0];
    float* out = (float*)d_out;

    cudaFuncSetAttribute(attn_kernel, cudaFuncAttributeMaxDynamicSharedMemorySize,
                         (int)sizeof(SmemA));

    attn_kernel<<<B, 256, sizeof(SmemA)>>>(
        user_id, item_id, item_category, item_dur_bkt,
        user_dense, item_dense, history_seq,
        user_W, item_W, cat_W, dur_W, hist_W,
        aW0, ab0, aW1, ab1, aW2, ab2);

    mlp_kernel<<<(B + 7) / 8, 256>>>(mW0, mb0, mW1, mb1, mW2, mb2, out, B);
}